// round 2
// baseline (speedup 1.0000x reference)
#include <cuda_runtime.h>

// MultiHeadAttentionQuantum — closed-form reduction (see R1 derivation):
//   c_u = cos(q_u + phi_u);  out_w = prod_{u<=w} c_u (w>=1);  out_0 = prod_{u=1..7} c_u
//   y = Wc @ out + bc.  k/v are dead code in the reference.
//
// R2 changes: __cosf (MUFU path) instead of libm cosf; x loads issued before
// smem fill + barrier to hide DRAM latency; block=128 so all 148 SMs are busy.

#define E_DIM 8

__global__ __launch_bounds__(128)
void mhaq_kernel(const float* __restrict__ x,
                 const float* __restrict__ Wq, const float* __restrict__ bq,
                 const float* __restrict__ Wc, const float* __restrict__ bc,
                 const float* __restrict__ phi,
                 float* __restrict__ out, int n_tok)
{
    __shared__ float sWq[64], sWc[64], sBq[8], sBc[8], sPhi[8];
    int tid = threadIdx.x;
    int t = blockIdx.x * blockDim.x + tid;

    // Issue the global x loads FIRST so their DRAM latency overlaps with the
    // weight staging + barrier below.
    float4 a = make_float4(0.f, 0.f, 0.f, 0.f), b = a;
    const float4* xv = reinterpret_cast<const float4*>(x);
    bool active = (t < n_tok);
    if (active) {
        a = xv[2 * t];
        b = xv[2 * t + 1];
    }

    // Stage the tiny weight set in shared (broadcast-read later, conflict-free).
    if (tid < 64) { sWq[tid] = Wq[tid]; sWc[tid] = Wc[tid]; }
    if (tid < 8)  { sBq[tid] = bq[tid]; sBc[tid] = bc[tid]; sPhi[tid] = phi[tid]; }
    __syncthreads();

    if (!active) return;

    float xr[8] = {a.x, a.y, a.z, a.w, b.x, b.y, b.z, b.w};

    // q = Wq @ x + bq, then c_u = cos(q_u + phi_u) via MUFU fast path.
    float c[8];
    #pragma unroll
    for (int u = 0; u < 8; u++) {
        float qv = sBq[u] + sPhi[u];
        #pragma unroll
        for (int e = 0; e < 8; e++) qv = fmaf(sWq[u * 8 + e], xr[e], qv);
        c[u] = __cosf(qv);
    }

    // Prefix products
    float o[8];
    float pre = c[0];
    #pragma unroll
    for (int w = 1; w < 8; w++) { pre *= c[w]; o[w] = pre; }
    float suf = c[1];
    #pragma unroll
    for (int w = 2; w < 8; w++) suf *= c[w];
    o[0] = suf;

    // y = Wc @ o + bc
    float y[8];
    #pragma unroll
    for (int u = 0; u < 8; u++) {
        float v = sBc[u];
        #pragma unroll
        for (int e = 0; e < 8; e++) v = fmaf(sWc[u * 8 + e], o[e], v);
        y[u] = v;
    }

    float4* ov = reinterpret_cast<float4*>(out);
    ov[2 * t]     = make_float4(y[0], y[1], y[2], y[3]);
    ov[2 * t + 1] = make_float4(y[4], y[5], y[6], y[7]);
}

extern "C" void kernel_launch(void* const* d_in, const int* in_sizes, int n_in,
                              void* d_out, int out_size)
{
    // metadata order: x, Wq, bq, Wk, bk, Wv, bv, Wc, bc, phi
    const float* x   = (const float*)d_in[0];
    const float* Wq  = (const float*)d_in[1];
    const float* bq  = (const float*)d_in[2];
    const float* Wc  = (const float*)d_in[7];
    const float* bc  = (const float*)d_in[8];
    const float* phi = (const float*)d_in[9];
    float* out = (float*)d_out;

    int n_tok = in_sizes[0] / E_DIM;   // 32768
    int threads = 128;
    int blocks = (n_tok + threads - 1) / threads;   // 256 blocks -> all SMs busy
    mhaq_kernel<<<blocks, threads>>>(x, Wq, bq, Wc, bc, phi, out, n_tok);
}